// round 8
// baseline (speedup 1.0000x reference)
#include <cuda_runtime.h>
#include <cstdint>

// ---------------------------------------------------------------------------
// RecurrentGCN (GConvGRU single step, h0 = 0) on GB300 sm_103 (non-'a' PTX
// target -> NO tcgen05; tensor path is mma.sync HMMA bf16).
//
// Math (exact given h0 == 0):
//   norm[e] = -rsqrt(deg[row]) * w[e] * rsqrt(deg[col])
//   tx1 = prop(x); tx2 = 2*prop(tx1) - x
//   y[50000,128] = [x|tx1|tx2] @ Wbig[192,128]  (cols 0-63 z, 64-127 h)
//   z = sigmoid(y_z + bz); ht = tanh(y_h + bh); t = tanh((1-z)*ht)
//   out = sigmoid(t @ Wlin + blin)
// GEMM: bf16 mma.sync with 3-term hi/lo split, K_eff = 3*192 = 576.
//   A_cat = [Ahi | Alo | Ahi], B_cat = [Bhi | Bhi | Blo]  (drop lo*lo)
// ---------------------------------------------------------------------------

namespace {
constexpr int NN = 50000;
constexpr int EE = 800000;
}

__device__ float g_deg[NN];
__device__ float g_dis[NN];
__device__ int   g_cnt[NN];
__device__ int   g_offs[NN + 1];
__device__ int   g_wpos[NN];
__device__ uint2 g_edge[EE];                       // {src, bits(nrm)}
__device__ float g_tx1[NN * 64];
__device__ float g_tx2[NN * 64];
__device__ __align__(16) unsigned char g_Wmma[9 * 16384];  // pre-swizzled bf16 B chunks
__device__ float g_bcomb[128];

// ---------------- helpers --------------------------------------------------
__device__ __forceinline__ uint32_t smem_to_u32(const void* p) {
  uint32_t a;
  asm("{ .reg .u64 t; cvta.to.shared.u64 t, %1; cvt.u32.u64 %0, t; }"
      : "=r"(a) : "l"(p));
  return a;
}
__device__ __forceinline__ float tanh_fast(float v) {
  float r;
  asm("tanh.approx.f32 %0, %1;" : "=f"(r) : "f"(v));
  return r;
}
__device__ __forceinline__ float sigmoid_fast(float v) {
  return 0.5f * tanh_fast(0.5f * v) + 0.5f;
}
__device__ __forceinline__ uint32_t bf2(float lo, float hi) {
  uint32_t r;  // packs: upper 16 = bf16(hi), lower 16 = bf16(lo)
  asm("cvt.rn.bf16x2.f32 %0, %1, %2;" : "=r"(r) : "f"(hi), "f"(lo));
  return r;
}
__device__ __forceinline__ unsigned short bf1(float v) {
  unsigned short r;
  asm("cvt.rn.bf16.f32 %0, %1;" : "=h"(r) : "f"(v));
  return r;
}
__device__ __forceinline__ void ldsm_x4(uint32_t* r, uint32_t addr) {
  asm volatile("ldmatrix.sync.aligned.m8n8.x4.shared.b16 {%0,%1,%2,%3}, [%4];"
               : "=r"(r[0]), "=r"(r[1]), "=r"(r[2]), "=r"(r[3]) : "r"(addr));
}
__device__ __forceinline__ void mma_bf16(float* d, const uint32_t* a,
                                         const uint32_t* b) {
  asm volatile(
      "mma.sync.aligned.m16n8k16.row.col.f32.bf16.bf16.f32 "
      "{%0,%1,%2,%3}, {%4,%5,%6,%7}, {%8,%9}, {%0,%1,%2,%3};"
      : "+f"(d[0]), "+f"(d[1]), "+f"(d[2]), "+f"(d[3])
      : "r"(a[0]), "r"(a[1]), "r"(a[2]), "r"(a[3]), "r"(b[0]), "r"(b[1]));
}

// ---------------------------------------------------------------------------
// K1: zero deg/cnt + pack pre-swizzled bf16 B chunks + combined bias
// Chunk c = term*3 + cheb, term 0/1 -> hi(W), term 2 -> lo(W).
// Layout per chunk: Bt[n=128][k=64] bf16, 128B rows, 16B-granule XOR swizzle.
__global__ void k_init(const float* __restrict__ Wxz, const float* __restrict__ Wxh,
                       const float* __restrict__ bxz, const float* __restrict__ bhz,
                       const float* __restrict__ bxh, const float* __restrict__ bhh) {
  int idx = blockIdx.x * blockDim.x + threadIdx.x;
  if (idx < NN) { g_deg[idx] = 0.0f; g_cnt[idx] = 0; }
  if (idx < 192 * 128) {
    int kg = idx >> 7;        // global k 0..191
    int n = idx & 127;
    int cheb = kg >> 6, kl = kg & 63;
    float w = (n < 64) ? Wxz[cheb * 4096 + kl * 64 + n]
                       : Wxh[cheb * 4096 + kl * 64 + (n - 64)];
    unsigned short hs = bf1(w);
    float hf = __uint_as_float((uint32_t)hs << 16);
    unsigned short ls = bf1(w - hf);
    uint32_t off = (uint32_t)n * 128 + ((((kl >> 3) ^ (n & 7)) << 4)) + (kl & 7) * 2;
    *(unsigned short*)(g_Wmma + (0 + cheb) * 16384 + off) = hs;
    *(unsigned short*)(g_Wmma + (3 + cheb) * 16384 + off) = hs;
    *(unsigned short*)(g_Wmma + (6 + cheb) * 16384 + off) = ls;
  }
  if (idx < 128) {
    g_bcomb[idx] = (idx < 64) ? (bxz[idx] + bhz[idx])
                              : (bxh[idx - 64] + bhh[idx - 64]);
  }
}

// K2: weighted out-degree + in-degree counts
__global__ void k_edge_accum(const int* __restrict__ ei, const float* __restrict__ w) {
  int e = blockIdx.x * blockDim.x + threadIdx.x;
  if (e >= EE) return;
  atomicAdd(&g_deg[ei[e]], w[e]);
  atomicAdd(&g_cnt[ei[EE + e]], 1);
}

// K3: dis = rsqrt(deg) + single-block exclusive scan of cnt -> offs/wpos
__device__ __forceinline__ int warp_incl_scan(int v, int lane) {
#pragma unroll
  for (int d = 1; d < 32; d <<= 1) {
    int t = __shfl_up_sync(0xFFFFFFFFu, v, d);
    if (lane >= d) v += t;
  }
  return v;
}

__global__ __launch_bounds__(1024) void k_scan() {
  constexpr int T = 1024, IPT = 16, CH = T * IPT;
  __shared__ int wsum[32];
  __shared__ int carry_s;
  int tid = threadIdx.x, lane = tid & 31, wid = tid >> 5;
  if (tid == 0) carry_s = 0;
  __syncthreads();
  int nCh = (NN + CH - 1) / CH;
  for (int ch = 0; ch < nCh; ch++) {
    int base = ch * CH + tid * IPT;
    int v[IPT];
#pragma unroll
    for (int j = 0; j < IPT; j++) {
      int i = base + j;
      if (i < NN) {
        v[j] = g_cnt[i];
        float dg = g_deg[i];
        g_dis[i] = (dg > 0.0f) ? rsqrtf(dg) : 0.0f;
      } else v[j] = 0;
    }
    int tsum = 0;
#pragma unroll
    for (int j = 0; j < IPT; j++) tsum += v[j];
    int incl = warp_incl_scan(tsum, lane);
    if (lane == 31) wsum[wid] = incl;
    __syncthreads();
    if (wid == 0) {
      int wv = wsum[lane];
      int wincl = warp_incl_scan(wv, lane);
      wsum[lane] = wincl - wv;
    }
    __syncthreads();
    int run = carry_s + wsum[wid] + (incl - tsum);
#pragma unroll
    for (int j = 0; j < IPT; j++) {
      int i = base + j;
      if (i < NN) { g_offs[i] = run; g_wpos[i] = run; }
      run += v[j];
    }
    __syncthreads();
    if (tid == T - 1) carry_s = run;
    __syncthreads();
  }
  if (tid == 0) g_offs[NN] = carry_s;
}

// K4: norm + CSR scatter, fused {src,nrm} 8B store
__global__ void k_edge_fill(const int* __restrict__ ei, const float* __restrict__ w) {
  int e = blockIdx.x * blockDim.x + threadIdx.x;
  if (e >= EE) return;
  int r = ei[e], c = ei[EE + e];
  float nrm = -g_dis[r] * w[e] * g_dis[c];
  int p = atomicAdd(&g_wpos[c], 1);
  g_edge[p] = make_uint2((uint32_t)r, __float_as_uint(nrm));
}

// K5/K6: warp-per-node CSR gather, MLP 8
__device__ __forceinline__ void prop_body(const float2* __restrict__ vf2,
                                          int s, int e, int lane,
                                          float& ax, float& ay) {
  int j = s;
  for (; j + 8 <= e; j += 8) {
    uint2 ed[8];
#pragma unroll
    for (int q = 0; q < 8; q++) ed[q] = g_edge[j + q];
    float2 v[8];
#pragma unroll
    for (int q = 0; q < 8; q++) v[q] = vf2[ed[q].x * 32 + lane];
#pragma unroll
    for (int q = 0; q < 8; q++) {
      float n = __uint_as_float(ed[q].y);
      ax += n * v[q].x; ay += n * v[q].y;
    }
  }
  if (j + 4 <= e) {
    uint2 ed[4];
#pragma unroll
    for (int q = 0; q < 4; q++) ed[q] = g_edge[j + q];
    float2 v[4];
#pragma unroll
    for (int q = 0; q < 4; q++) v[q] = vf2[ed[q].x * 32 + lane];
#pragma unroll
    for (int q = 0; q < 4; q++) {
      float n = __uint_as_float(ed[q].y);
      ax += n * v[q].x; ay += n * v[q].y;
    }
    j += 4;
  }
  for (; j < e; j++) {
    uint2 ed = g_edge[j];
    float2 v = vf2[ed.x * 32 + lane];
    float n = __uint_as_float(ed.y);
    ax += n * v.x; ay += n * v.y;
  }
}

__global__ __launch_bounds__(256) void k_prop1(const float* __restrict__ x) {
  int gw = (blockIdx.x * blockDim.x + threadIdx.x) >> 5;
  int lane = threadIdx.x & 31;
  if (gw >= NN) return;
  int s = g_offs[gw], e = g_offs[gw + 1];
  float ax = 0.f, ay = 0.f;
  prop_body(reinterpret_cast<const float2*>(x), s, e, lane, ax, ay);
  reinterpret_cast<float2*>(g_tx1)[gw * 32 + lane] = make_float2(ax, ay);
}

__global__ __launch_bounds__(256) void k_prop2(const float* __restrict__ x) {
  int gw = (blockIdx.x * blockDim.x + threadIdx.x) >> 5;
  int lane = threadIdx.x & 31;
  if (gw >= NN) return;
  int s = g_offs[gw], e = g_offs[gw + 1];
  float ax = 0.f, ay = 0.f;
  prop_body(reinterpret_cast<const float2*>(g_tx1), s, e, lane, ax, ay);
  float2 xv = reinterpret_cast<const float2*>(x)[gw * 32 + lane];
  reinterpret_cast<float2*>(g_tx2)[gw * 32 + lane] =
      make_float2(2.0f * ax - xv.x, 2.0f * ay - xv.y);
}

// ---------------------------------------------------------------------------
// K7: mma.sync bf16 GEMM tile (128m x 128n x 576k) + gates + head.
// 256 threads = 8 warps; warpM = wid&1 (64 rows), warpN = wid>>1 (32 cols).
// SMEM (dynamic, 67584 B):
//   chunk phase:   A [0,16K)  B [16K,32K)    (bf16, swizzled 128B rows)
//   epilogue:      Y [0,66560)  fp32 [128][130],  P [66560, +1024) partials
static constexpr uint32_t A_OFF = 0;
static constexpr uint32_t B_OFF = 16384;
static constexpr uint32_t P_OFF = 66560;
static constexpr uint32_t SMEM_GEMM = 67584;

extern __shared__ char smem_dyn[];

__global__ __launch_bounds__(256, 2) void k_gemm_tc(const float* __restrict__ x,
                                                    const float* __restrict__ Wlin,
                                                    const float* __restrict__ blin,
                                                    float* __restrict__ out) {
  char* smem = smem_dyn;
  uint32_t sA = smem_to_u32(smem) + A_OFF;
  uint32_t sB = smem_to_u32(smem) + B_OFF;
  int tid = threadIdx.x;
  int wid = tid >> 5, lane = tid & 31;
  int warpM = wid & 1, warpN = wid >> 1;

  float acc[4][4][4];
#pragma unroll
  for (int mi = 0; mi < 4; mi++)
#pragma unroll
    for (int j = 0; j < 4; j++)
#pragma unroll
      for (int q = 0; q < 4; q++) acc[mi][j][q] = 0.0f;

  // A staging indices: thread -> row m, k-half
  int am = tid >> 1, ahalf = tid & 1;
  int node = blockIdx.x * 128 + am;
  if (node >= NN) node = NN - 1;

  int matq = lane >> 3, rq = lane & 7;

#pragma unroll 1
  for (int c = 0; c < 9; c++) {
    int cheb = (c >= 6) ? c - 6 : (c >= 3) ? c - 3 : c;
    bool isLo = (c >= 3 && c < 6);  // term 1 -> lo(A)
    // ---- stage B chunk (pre-swizzled, linear 16B copies) ----
    {
      const uint4* bs = reinterpret_cast<const uint4*>(g_Wmma + c * 16384);
      uint4* bd = reinterpret_cast<uint4*>(smem + B_OFF);
#pragma unroll
      for (int q = 0; q < 4; q++) bd[tid + q * 256] = bs[tid + q * 256];
    }
    // ---- stage A chunk with fp32 -> bf16 hi/lo conversion ----
    {
      const float* src = (cheb == 0) ? x : (cheb == 1) ? g_tx1 : g_tx2;
      const float4* row =
          reinterpret_cast<const float4*>(src + node * 64 + ahalf * 32);
      char* ab = smem + A_OFF;
#pragma unroll
      for (int g = 0; g < 4; g++) {
        float4 f0 = row[g * 2], f1 = row[g * 2 + 1];
        uint32_t h0 = bf2(f0.x, f0.y), h1 = bf2(f0.z, f0.w);
        uint32_t h2 = bf2(f1.x, f1.y), h3 = bf2(f1.z, f1.w);
        uint4 val;
        if (isLo) {
          float r0 = f0.x - __uint_as_float(h0 << 16);
          float r1 = f0.y - __uint_as_float(h0 & 0xFFFF0000u);
          float r2 = f0.z - __uint_as_float(h1 << 16);
          float r3 = f0.w - __uint_as_float(h1 & 0xFFFF0000u);
          float r4 = f1.x - __uint_as_float(h2 << 16);
          float r5 = f1.y - __uint_as_float(h2 & 0xFFFF0000u);
          float r6 = f1.z - __uint_as_float(h3 << 16);
          float r7 = f1.w - __uint_as_float(h3 & 0xFFFF0000u);
          val = make_uint4(bf2(r0, r1), bf2(r2, r3), bf2(r4, r5), bf2(r6, r7));
        } else {
          val = make_uint4(h0, h1, h2, h3);
        }
        int kg = ahalf * 4 + g;  // k>>3 within chunk
        *(uint4*)(ab + am * 128 + ((kg ^ (am & 7)) << 4)) = val;
      }
    }
    __syncthreads();

    // ---- compute: 4 k16-steps ----
#pragma unroll
    for (int ks = 0; ks < 4; ks++) {
      uint32_t a[4][4], b[4][2];
#pragma unroll
      for (int mi = 0; mi < 4; mi++) {
        int arow = warpM * 64 + mi * 16 + ((matq & 1) << 3) + rq;
        int k8 = ks * 2 + (matq >> 1);
        ldsm_x4(a[mi], sA + arow * 128 + ((k8 ^ (arow & 7)) << 4));
      }
#pragma unroll
      for (int jp = 0; jp < 2; jp++) {
        int nrow = warpN * 32 + jp * 16 + ((matq >> 1) << 3) + rq;
        int k8 = ks * 2 + (matq & 1);
        uint32_t t4[4];
        ldsm_x4(t4, sB + nrow * 128 + ((k8 ^ (nrow & 7)) << 4));
        b[jp * 2][0] = t4[0]; b[jp * 2][1] = t4[1];
        b[jp * 2 + 1][0] = t4[2]; b[jp * 2 + 1][1] = t4[3];
      }
#pragma unroll
      for (int mi = 0; mi < 4; mi++)
#pragma unroll
        for (int j = 0; j < 4; j++) mma_bf16(acc[mi][j], a[mi], b[j]);
    }
    __syncthreads();
  }

  // ---- write accumulators to smem Y[128][130] fp32 ----
  float* Y = reinterpret_cast<float*>(smem);
  {
    int gid = lane >> 2, tig = lane & 3;
#pragma unroll
    for (int mi = 0; mi < 4; mi++) {
      int row = warpM * 64 + mi * 16 + gid;
#pragma unroll
      for (int j = 0; j < 4; j++) {
        int col = warpN * 32 + j * 8 + tig * 2;
        Y[row * 130 + col] = acc[mi][j][0];
        Y[row * 130 + col + 1] = acc[mi][j][1];
        Y[(row + 8) * 130 + col] = acc[mi][j][2];
        Y[(row + 8) * 130 + col + 1] = acc[mi][j][3];
      }
    }
  }
  __syncthreads();

  // ---- gates + head: thread (half, m) covers dims [half*32, half*32+32) ----
  {
    int half = tid >> 7, m = tid & 127;
    int cb = half * 32;
    float d0 = 0.f, d1 = 0.f;
#pragma unroll
    for (int q = 0; q < 32; q++) {
      int dim = cb + q;
      float z = sigmoid_fast(Y[m * 130 + dim] + g_bcomb[dim]);
      float ht = tanh_fast(Y[m * 130 + 64 + dim] + g_bcomb[64 + dim]);
      float t = tanh_fast((1.0f - z) * ht);
      d0 += t * Wlin[dim * 2];
      d1 += t * Wlin[dim * 2 + 1];
    }
    float2* P = reinterpret_cast<float2*>(smem + P_OFF);
    if (half) P[m] = make_float2(d0, d1);
    __syncthreads();
    if (!half) {
      int onode = blockIdx.x * 128 + m;
      if (onode < NN) {
        float2 p = P[m];
        float v0 = d0 + p.x + blin[0];
        float v1 = d1 + p.y + blin[1];
        float o0 = 1.0f / (1.0f + __expf(-v0));
        float o1 = 1.0f / (1.0f + __expf(-v1));
        *(float2*)(out + onode * 2) = make_float2(o0, o1);
      }
    }
  }
}

// ---------------------------------------------------------------------------
extern "C" void kernel_launch(void* const* d_in, const int* in_sizes, int n_in,
                              void* d_out, int out_size) {
  const float* x    = (const float*)d_in[0];
  const int*   ei   = (const int*)d_in[1];
  const float* w    = (const float*)d_in[2];
  const float* Wxz  = (const float*)d_in[3];
  const float* bxz  = (const float*)d_in[4];
  const float* bhz  = (const float*)d_in[6];
  const float* Wxh  = (const float*)d_in[11];
  const float* bxh  = (const float*)d_in[12];
  const float* bhh  = (const float*)d_in[14];
  const float* Wlin = (const float*)d_in[15];
  const float* blin = (const float*)d_in[16];
  float* out = (float*)d_out;

  cudaFuncSetAttribute(k_gemm_tc, cudaFuncAttributeMaxDynamicSharedMemorySize,
                       SMEM_GEMM);

  k_init<<<(NN + 255) / 256, 256>>>(Wxz, Wxh, bxz, bhz, bxh, bhh);
  k_edge_accum<<<(EE + 255) / 256, 256>>>(ei, w);
  k_scan<<<1, 1024>>>();
  k_edge_fill<<<(EE + 255) / 256, 256>>>(ei, w);
  k_prop1<<<(NN * 32 + 255) / 256, 256>>>(x);
  k_prop2<<<(NN * 32 + 255) / 256, 256>>>(x);
  k_gemm_tc<<<(NN + 127) / 128, 256, SMEM_GEMM>>>(x, Wlin, blin, out);
}

// round 9
// speedup vs baseline: 1.2248x; 1.2248x over previous
#include <cuda_runtime.h>
#include <cuda_fp16.h>
#include <cstdint>

// ---------------------------------------------------------------------------
// RecurrentGCN (GConvGRU single step, h0 = 0) on GB300 (sm_103 PTX target,
// no tcgen05 -> mma.sync HMMA fp16 path).
//
// Math (exact given h0 == 0):
//   norm[e] = -rsqrt(deg[row]) * w[e] * rsqrt(deg[col])
//   tx1 = prop(x); tx2 = 2*prop(tx1) - x
//   y[50000,128] = [x|tx1|tx2] @ Wbig[192,128]  (cols 0-63 z, 64-127 h)
//   z = sigmoid(y_z+bz); ht = tanh(y_h+bh); t = tanh((1-z)*ht)
//   out = sigmoid(t @ Wlin + blin)
// Numerics: A (features) in fp16; W split W = Whi + Wlo (both fp16);
//   y = A@Whi + A@Wlo  -> error ~ eps_fp16(A) ~ 1.7e-4 rel (threshold 1e-3).
// Props gather fp16 rows (128B/row -> 5 L1 wavefronts/edge vs 9 for fp32).
// ---------------------------------------------------------------------------

namespace {
constexpr int NN = 50000;
constexpr int EE = 800000;
}

__device__ float g_deg[NN];
__device__ float g_dis[NN];
__device__ int   g_cnt[NN];
__device__ int   g_offs[NN + 1];
__device__ int   g_wpos[NN];
__device__ uint2 g_edge[EE];                    // {src, bits(nrm)}
// fp16 feature sections: 0 = x, 1 = tx1, 2 = tx2; [sec][node][64]
__device__ __align__(16) __half g_Ahi[3 * NN * 64];
// pre-swizzled fp16 W chunks: order Bh0,Bl0,Bh1,Bl1,Bh2,Bl2 (16KB each)
__device__ __align__(16) unsigned char g_Bpack[6 * 16384];
__device__ float g_bcomb[128];

// ---------------- helpers --------------------------------------------------
__device__ __forceinline__ uint32_t smem_to_u32(const void* p) {
  uint32_t a;
  asm("{ .reg .u64 t; cvta.to.shared.u64 t, %1; cvt.u32.u64 %0, t; }"
      : "=r"(a) : "l"(p));
  return a;
}
__device__ __forceinline__ float tanh_fast(float v) {
  float r;
  asm("tanh.approx.f32 %0, %1;" : "=f"(r) : "f"(v));
  return r;
}
__device__ __forceinline__ float sigmoid_fast(float v) {
  return 0.5f * tanh_fast(0.5f * v) + 0.5f;
}
__device__ __forceinline__ void ldsm_x4(uint32_t* r, uint32_t addr) {
  asm volatile("ldmatrix.sync.aligned.m8n8.x4.shared.b16 {%0,%1,%2,%3}, [%4];"
               : "=r"(r[0]), "=r"(r[1]), "=r"(r[2]), "=r"(r[3]) : "r"(addr));
}
__device__ __forceinline__ void mma_fp16(float* d, const uint32_t* a,
                                         const uint32_t* b) {
  asm volatile(
      "mma.sync.aligned.m16n8k16.row.col.f32.f16.f16.f32 "
      "{%0,%1,%2,%3}, {%4,%5,%6,%7}, {%8,%9}, {%0,%1,%2,%3};"
      : "+f"(d[0]), "+f"(d[1]), "+f"(d[2]), "+f"(d[3])
      : "r"(a[0]), "r"(a[1]), "r"(a[2]), "r"(a[3]), "r"(b[0]), "r"(b[1]));
}
__device__ __forceinline__ void cp_async16(uint32_t dst, const void* src) {
  asm volatile("cp.async.cg.shared.global [%0], [%1], 16;"
               :: "r"(dst), "l"(src));
}
#define CP_COMMIT() asm volatile("cp.async.commit_group;" ::: "memory")
#define CP_WAIT(N) asm volatile("cp.async.wait_group %0;" :: "n"(N) : "memory")

// ---------------------------------------------------------------------------
// K1: zero deg/cnt + pack fp16 hi/lo W chunks + combined bias + x -> fp16
__global__ void k_init(const float* __restrict__ x,
                       const float* __restrict__ Wxz, const float* __restrict__ Wxh,
                       const float* __restrict__ bxz, const float* __restrict__ bhz,
                       const float* __restrict__ bxh, const float* __restrict__ bhh) {
  int idx = blockIdx.x * blockDim.x + threadIdx.x;
  if (idx < NN) { g_deg[idx] = 0.0f; g_cnt[idx] = 0; }
  if (idx < 192 * 128) {
    int kg = idx >> 7;  // global k 0..191
    int n = idx & 127;
    int cheb = kg >> 6, kl = kg & 63;
    float w = (n < 64) ? Wxz[cheb * 4096 + kl * 64 + n]
                       : Wxh[cheb * 4096 + kl * 64 + (n - 64)];
    __half hi = __float2half_rn(w);
    __half lo = __float2half_rn(w - __half2float(hi));
    uint32_t off = (uint32_t)n * 128 + ((((kl >> 3) ^ (n & 7)) << 4)) + (kl & 7) * 2;
    *(__half*)(g_Bpack + (2 * cheb + 0) * 16384 + off) = hi;
    *(__half*)(g_Bpack + (2 * cheb + 1) * 16384 + off) = lo;
  }
  if (idx < 128) {
    g_bcomb[idx] = (idx < 64) ? (bxz[idx] + bhz[idx])
                              : (bxh[idx - 64] + bhh[idx - 64]);
  }
  if (idx < NN * 32) {  // x -> fp16 section 0 (pairwise)
    float2 v = reinterpret_cast<const float2*>(x)[idx];
    reinterpret_cast<__half2*>(g_Ahi)[idx] = __float22half2_rn(v);
  }
}

// K2: weighted out-degree + in-degree counts
__global__ void k_edge_accum(const int* __restrict__ ei, const float* __restrict__ w) {
  int e = blockIdx.x * blockDim.x + threadIdx.x;
  if (e >= EE) return;
  atomicAdd(&g_deg[ei[e]], w[e]);
  atomicAdd(&g_cnt[ei[EE + e]], 1);
}

// K3: dis = rsqrt(deg) + single-block exclusive scan of cnt -> offs/wpos
__device__ __forceinline__ int warp_incl_scan(int v, int lane) {
#pragma unroll
  for (int d = 1; d < 32; d <<= 1) {
    int t = __shfl_up_sync(0xFFFFFFFFu, v, d);
    if (lane >= d) v += t;
  }
  return v;
}

__global__ __launch_bounds__(1024) void k_scan() {
  constexpr int T = 1024, IPT = 16, CH = T * IPT;
  __shared__ int wsum[32];
  __shared__ int carry_s;
  int tid = threadIdx.x, lane = tid & 31, wid = tid >> 5;
  if (tid == 0) carry_s = 0;
  __syncthreads();
  int nCh = (NN + CH - 1) / CH;
  for (int ch = 0; ch < nCh; ch++) {
    int base = ch * CH + tid * IPT;
    int v[IPT];
#pragma unroll
    for (int j = 0; j < IPT; j++) {
      int i = base + j;
      if (i < NN) {
        v[j] = g_cnt[i];
        float dg = g_deg[i];
        g_dis[i] = (dg > 0.0f) ? rsqrtf(dg) : 0.0f;
      } else v[j] = 0;
    }
    int tsum = 0;
#pragma unroll
    for (int j = 0; j < IPT; j++) tsum += v[j];
    int incl = warp_incl_scan(tsum, lane);
    if (lane == 31) wsum[wid] = incl;
    __syncthreads();
    if (wid == 0) {
      int wv = wsum[lane];
      int wincl = warp_incl_scan(wv, lane);
      wsum[lane] = wincl - wv;
    }
    __syncthreads();
    int run = carry_s + wsum[wid] + (incl - tsum);
#pragma unroll
    for (int j = 0; j < IPT; j++) {
      int i = base + j;
      if (i < NN) { g_offs[i] = run; g_wpos[i] = run; }
      run += v[j];
    }
    __syncthreads();
    if (tid == T - 1) carry_s = run;
    __syncthreads();
  }
  if (tid == 0) g_offs[NN] = carry_s;
}

// K4: norm + CSR scatter, fused {src,nrm} 8B store
__global__ void k_edge_fill(const int* __restrict__ ei, const float* __restrict__ w) {
  int e = blockIdx.x * blockDim.x + threadIdx.x;
  if (e >= EE) return;
  int r = ei[e], c = ei[EE + e];
  float nrm = -g_dis[r] * w[e] * g_dis[c];
  int p = atomicAdd(&g_wpos[c], 1);
  g_edge[p] = make_uint2((uint32_t)r, __float_as_uint(nrm));
}

// K5/K6: warp-per-node CSR gather over fp16 rows (128B/row), MLP 8
__device__ __forceinline__ void prop_body(const __half2* __restrict__ vf,
                                          int s, int e, int lane,
                                          float& ax, float& ay) {
  int j = s;
  for (; j + 8 <= e; j += 8) {
    uint2 ed[8];
#pragma unroll
    for (int q = 0; q < 8; q++) ed[q] = g_edge[j + q];
    __half2 v[8];
#pragma unroll
    for (int q = 0; q < 8; q++) v[q] = vf[ed[q].x * 32 + lane];
#pragma unroll
    for (int q = 0; q < 8; q++) {
      float n = __uint_as_float(ed[q].y);
      float2 f = __half22float2(v[q]);
      ax += n * f.x; ay += n * f.y;
    }
  }
  if (j + 4 <= e) {
    uint2 ed[4];
#pragma unroll
    for (int q = 0; q < 4; q++) ed[q] = g_edge[j + q];
    __half2 v[4];
#pragma unroll
    for (int q = 0; q < 4; q++) v[q] = vf[ed[q].x * 32 + lane];
#pragma unroll
    for (int q = 0; q < 4; q++) {
      float n = __uint_as_float(ed[q].y);
      float2 f = __half22float2(v[q]);
      ax += n * f.x; ay += n * f.y;
    }
    j += 4;
  }
  for (; j < e; j++) {
    uint2 ed = g_edge[j];
    float2 f = __half22float2(vf[ed.x * 32 + lane]);
    float n = __uint_as_float(ed.y);
    ax += n * f.x; ay += n * f.y;
  }
}

__global__ __launch_bounds__(256) void k_prop1() {
  int gw = (blockIdx.x * blockDim.x + threadIdx.x) >> 5;
  int lane = threadIdx.x & 31;
  if (gw >= NN) return;
  int s = g_offs[gw], e = g_offs[gw + 1];
  float ax = 0.f, ay = 0.f;
  prop_body(reinterpret_cast<const __half2*>(g_Ahi), s, e, lane, ax, ay);
  reinterpret_cast<__half2*>(g_Ahi + (size_t)NN * 64)[gw * 32 + lane] =
      __float22half2_rn(make_float2(ax, ay));
}

__global__ __launch_bounds__(256) void k_prop2(const float* __restrict__ x) {
  int gw = (blockIdx.x * blockDim.x + threadIdx.x) >> 5;
  int lane = threadIdx.x & 31;
  if (gw >= NN) return;
  int s = g_offs[gw], e = g_offs[gw + 1];
  float ax = 0.f, ay = 0.f;
  prop_body(reinterpret_cast<const __half2*>(g_Ahi + (size_t)NN * 64),
            s, e, lane, ax, ay);
  float2 xv = reinterpret_cast<const float2*>(x)[gw * 32 + lane];
  reinterpret_cast<__half2*>(g_Ahi + (size_t)2 * NN * 64)[gw * 32 + lane] =
      __float22half2_rn(make_float2(2.0f * ax - xv.x, 2.0f * ay - xv.y));
}

// ---------------------------------------------------------------------------
// K7: mma.sync fp16 GEMM (128m x 128n, K = 3x64, W hi+lo merged per stage)
// SMEM: A [0,16K) | B [16K, 16K+96K): Bh0,Bl0,Bh1,Bl1,Bh2,Bl2 (cp.async).
// Epilogue overlays Y[128][130] fp32 at base, P partials at 66560.
static constexpr uint32_t A_OFF = 0;
static constexpr uint32_t B_OFF = 16384;
static constexpr uint32_t P_OFF = 66560;
static constexpr uint32_t SMEM_GEMM = 16384 + 6 * 16384;  // 114688

extern __shared__ char smem_dyn[];

__global__ __launch_bounds__(256, 2) void k_gemm(const float* __restrict__ Wlin,
                                                 const float* __restrict__ blin,
                                                 float* __restrict__ out) {
  char* smem = smem_dyn;
  uint32_t sA = smem_to_u32(smem) + A_OFF;
  uint32_t sB = smem_to_u32(smem) + B_OFF;
  int tid = threadIdx.x;
  int wid = tid >> 5, lane = tid & 31;
  int warpM = wid & 1, warpN = wid >> 1;
  int matq = lane >> 3, rq = lane & 7;

  float acc[4][4][4];
#pragma unroll
  for (int mi = 0; mi < 4; mi++)
#pragma unroll
    for (int j = 0; j < 4; j++)
#pragma unroll
      for (int q = 0; q < 4; q++) acc[mi][j][q] = 0.0f;

  // A staging coordinates
  int am = tid >> 1, ahalf = tid & 1;
  int node = blockIdx.x * 128 + am;
  if (node >= NN) node = NN - 1;

  // issue all 6 B chunk copies (in-order group commits)
#pragma unroll
  for (int i = 0; i < 6; i++) {
    const char* src = (const char*)g_Bpack + i * 16384 + tid * 16;
    uint32_t dst = sB + i * 16384 + tid * 16;
#pragma unroll
    for (int q = 0; q < 4; q++) cp_async16(dst + q * 4096, src + q * 4096);
    CP_COMMIT();
  }

#pragma unroll 1
  for (int s = 0; s < 3; s++) {
    // ---- stage A (LDG -> swizzled STS), 64B per thread ----
    const __half* asec = g_Ahi + (size_t)s * NN * 64 + (size_t)node * 64 + ahalf * 32;
    uint4 av[4];
#pragma unroll
    for (int g = 0; g < 4; g++)
      av[g] = *reinterpret_cast<const uint4*>(asec + g * 8);
    if (s > 0) __syncthreads();  // previous compute done before overwrite
#pragma unroll
    for (int g = 0; g < 4; g++) {
      int kg = ahalf * 4 + g;
      *reinterpret_cast<uint4*>(smem + A_OFF + am * 128 +
                                ((kg ^ (am & 7)) << 4)) = av[g];
    }
    if (s == 0) { CP_WAIT(4); }
    else if (s == 1) { CP_WAIT(2); }
    else { CP_WAIT(0); }
    __syncthreads();

    uint32_t sBh = sB + (2 * s) * 16384;
    uint32_t sBl = sB + (2 * s + 1) * 16384;
    // ---- compute: 4 k16-steps, A frags shared by both W terms ----
#pragma unroll
    for (int ks = 0; ks < 4; ks++) {
      uint32_t a[4][4], bh[4][2], bl[4][2];
#pragma unroll
      for (int mi = 0; mi < 4; mi++) {
        int arow = warpM * 64 + mi * 16 + ((matq & 1) << 3) + rq;
        int k8 = ks * 2 + (matq >> 1);
        ldsm_x4(a[mi], sA + arow * 128 + ((k8 ^ (arow & 7)) << 4));
      }
#pragma unroll
      for (int jp = 0; jp < 2; jp++) {
        int nrow = warpN * 32 + jp * 16 + ((matq >> 1) << 3) + rq;
        int k8 = ks * 2 + (matq & 1);
        uint32_t off = nrow * 128 + ((k8 ^ (nrow & 7)) << 4);
        uint32_t t4[4];
        ldsm_x4(t4, sBh + off);
        bh[jp * 2][0] = t4[0]; bh[jp * 2][1] = t4[1];
        bh[jp * 2 + 1][0] = t4[2]; bh[jp * 2 + 1][1] = t4[3];
        ldsm_x4(t4, sBl + off);
        bl[jp * 2][0] = t4[0]; bl[jp * 2][1] = t4[1];
        bl[jp * 2 + 1][0] = t4[2]; bl[jp * 2 + 1][1] = t4[3];
      }
#pragma unroll
      for (int mi = 0; mi < 4; mi++)
#pragma unroll
        for (int j = 0; j < 4; j++) {
          mma_fp16(acc[mi][j], a[mi], bh[j]);
          mma_fp16(acc[mi][j], a[mi], bl[j]);
        }
    }
  }
  __syncthreads();

  // ---- write accumulators to smem Y[128][130] fp32 ----
  float* Y = reinterpret_cast<float*>(smem);
  {
    int gid = lane >> 2, tig = lane & 3;
#pragma unroll
    for (int mi = 0; mi < 4; mi++) {
      int row = warpM * 64 + mi * 16 + gid;
#pragma unroll
      for (int j = 0; j < 4; j++) {
        int col = warpN * 32 + j * 8 + tig * 2;
        Y[row * 130 + col] = acc[mi][j][0];
        Y[row * 130 + col + 1] = acc[mi][j][1];
        Y[(row + 8) * 130 + col] = acc[mi][j][2];
        Y[(row + 8) * 130 + col + 1] = acc[mi][j][3];
      }
    }
  }
  __syncthreads();

  // ---- gates + head ----
  {
    int half = tid >> 7, m = tid & 127;
    int cb = half * 32;
    float d0 = 0.f, d1 = 0.f;
#pragma unroll
    for (int q = 0; q < 32; q++) {
      int dim = cb + q;
      float z = sigmoid_fast(Y[m * 130 + dim] + g_bcomb[dim]);
      float ht = tanh_fast(Y[m * 130 + 64 + dim] + g_bcomb[64 + dim]);
      float t = tanh_fast((1.0f - z) * ht);
      d0 += t * Wlin[dim * 2];
      d1 += t * Wlin[dim * 2 + 1];
    }
    float2* P = reinterpret_cast<float2*>(smem + P_OFF);
    if (half) P[m] = make_float2(d0, d1);
    __syncthreads();
    if (!half) {
      int onode = blockIdx.x * 128 + m;
      if (onode < NN) {
        float2 p = P[m];
        float v0 = d0 + p.x + blin[0];
        float v1 = d1 + p.y + blin[1];
        float o0 = 1.0f / (1.0f + __expf(-v0));
        float o1 = 1.0f / (1.0f + __expf(-v1));
        *(float2*)(out + onode * 2) = make_float2(o0, o1);
      }
    }
  }
}

// ---------------------------------------------------------------------------
extern "C" void kernel_launch(void* const* d_in, const int* in_sizes, int n_in,
                              void* d_out, int out_size) {
  const float* x    = (const float*)d_in[0];
  const int*   ei   = (const int*)d_in[1];
  const float* w    = (const float*)d_in[2];
  const float* Wxz  = (const float*)d_in[3];
  const float* bxz  = (const float*)d_in[4];
  const float* bhz  = (const float*)d_in[6];
  const float* Wxh  = (const float*)d_in[11];
  const float* bxh  = (const float*)d_in[12];
  const float* bhh  = (const float*)d_in[14];
  const float* Wlin = (const float*)d_in[15];
  const float* blin = (const float*)d_in[16];
  float* out = (float*)d_out;

  cudaFuncSetAttribute(k_gemm, cudaFuncAttributeMaxDynamicSharedMemorySize,
                       SMEM_GEMM);

  k_init<<<(NN * 32 + 255) / 256, 256>>>(x, Wxz, Wxh, bxz, bhz, bxh, bhh);
  k_edge_accum<<<(EE + 255) / 256, 256>>>(ei, w);
  k_scan<<<1, 1024>>>();
  k_edge_fill<<<(EE + 255) / 256, 256>>>(ei, w);
  k_prop1<<<(NN * 32 + 255) / 256, 256>>>();
  k_prop2<<<(NN * 32 + 255) / 256, 256>>>(x);
  k_gemm<<<(NN + 127) / 128, 256, SMEM_GEMM>>>(Wlin, blin, out);
}